// round 16
// baseline (speedup 1.0000x reference)
#include <cuda_runtime.h>
#include <cuda_bf16.h>
#include <cuda_fp16.h>
#include <cstdint>

static constexpr int BDIM = 4096;
static constexpr int IDIM = 1024;
static constexpr int HDIM = 2048;
static constexpr int NSTEPS = 10;
static constexpr float DT = 0.1f;

static constexpr int BM = 128, BN = 64, BK = 32;
static constexpr int NT = 256;

// ---- ih kernel (2-term): stage [A16 8K | Abf 8K | Bhi 4K | Blo 4K] = 24 KB, 3 stages
static constexpr int A_PLANE = BM * BK * 2;            // 8 KB
static constexpr int B_PLANE = BN * BK * 2;            // 4 KB
static constexpr int STAGE_BYTES = 2 * A_PLANE + 2 * B_PLANE;   // 24 KB
static constexpr int OFF_BPL = 2 * A_PLANE;            // 16 KB
static constexpr int OFF_COLV = 3 * STAGE_BYTES;       // 72 KB
static constexpr int SMEM_TOTAL = OFF_COLV + BN * 4 + 16;

// ---- step kernel v2 (1-term fp16, BN=128, warp tile 64x32):
//      stage [A16 8K | B16 8K] = 16 KB, 3 stages
static constexpr int S_BN = 128;
static constexpr int S_STAGE = 2 * A_PLANE;            // 16 KB
static constexpr int S_OFF_B = A_PLANE;                // 8 KB
static constexpr int S_OFF_COLV = 3 * S_STAGE;         // 48 KB
static constexpr int S_SMEM_TOTAL = S_OFF_COLV + S_BN * 4 + 16;   // ~48.5 KB -> occ 4

__device__ float g_ihb  [BDIM * HDIM];
__device__ float g_hfull[BDIM * HDIM];
__device__ __half        g_h16A[BDIM * HDIM];
__device__ __half        g_h16B[BDIM * HDIM];
__device__ __half        g_x16 [BDIM * IDIM];
__device__ __nv_bfloat16 g_xbf [BDIM * IDIM];
__device__ __half        g_wihhi[HDIM * IDIM];
__device__ __nv_bfloat16 g_wihlo[HDIM * IDIM];
__device__ __half        g_whhhi[HDIM * HDIM];

__device__ __forceinline__ uint32_t smem_u32(const void* p) {
    uint32_t a;
    asm("{ .reg .u64 t; cvta.to.shared.u64 t, %1; cvt.u32.u64 %0, t; }" : "=r"(a) : "l"(p));
    return a;
}
__device__ __forceinline__ void cp16(uint32_t dst, const void* src) {
    asm volatile("cp.async.cg.shared.global [%0], [%1], 16;" :: "r"(dst), "l"(src) : "memory");
}
__device__ __forceinline__ void cp_commit() { asm volatile("cp.async.commit_group;" ::: "memory"); }
template <int N> __device__ __forceinline__ void cp_wait() {
    asm volatile("cp.async.wait_group %0;" :: "n"(N) : "memory");
}
__device__ __forceinline__ float tanh_acc(float x) {
    float ax = fabsf(x);
    float e = __expf(-2.0f * ax);
    float t = (1.0f - e) / (1.0f + e);
    return copysignf(t, x);
}
__device__ __forceinline__ void mma_f16(float* c, const uint32_t* a, const uint32_t* b) {
    asm volatile(
        "mma.sync.aligned.m16n8k16.row.col.f32.f16.f16.f32 "
        "{%0,%1,%2,%3},{%4,%5,%6,%7},{%8,%9},{%0,%1,%2,%3};"
        : "+f"(c[0]), "+f"(c[1]), "+f"(c[2]), "+f"(c[3])
        : "r"(a[0]), "r"(a[1]), "r"(a[2]), "r"(a[3]), "r"(b[0]), "r"(b[1]));
}
__device__ __forceinline__ void mma_bf16(float* c, const uint32_t* a, const uint32_t* b) {
    asm volatile(
        "mma.sync.aligned.m16n8k16.row.col.f32.bf16.bf16.f32 "
        "{%0,%1,%2,%3},{%4,%5,%6,%7},{%8,%9},{%0,%1,%2,%3};"
        : "+f"(c[0]), "+f"(c[1]), "+f"(c[2]), "+f"(c[3])
        : "r"(a[0]), "r"(a[1]), "r"(a[2]), "r"(a[3]), "r"(b[0]), "r"(b[1]));
}
__device__ __forceinline__ void ldsm4(uint32_t* r, uint32_t addr) {
    asm volatile("ldmatrix.sync.aligned.m8n8.x4.shared.b16 {%0,%1,%2,%3}, [%4];"
                 : "=r"(r[0]), "=r"(r[1]), "=r"(r[2]), "=r"(r[3]) : "r"(addr));
}
__device__ __forceinline__ void splitW(float v, __half& hi, __nv_bfloat16& lo) {
    hi = __float2half_rn(v);
    lo = __float2bfloat16(v - __half2float(hi));
}

__global__ void prep_all_kernel(const float* __restrict__ x,
                                const float* __restrict__ Wih,
                                const float* __restrict__ Whh,
                                const float* __restrict__ h0,
                                __half* __restrict__ x16, __nv_bfloat16* __restrict__ xbf,
                                __half* __restrict__ wihhi, __nv_bfloat16* __restrict__ wihlo,
                                __half* __restrict__ whhhi,
                                float* __restrict__ hfull, __half* __restrict__ h16) {
    const int stride = gridDim.x * blockDim.x;
    const int t0 = blockIdx.x * blockDim.x + threadIdx.x;
    for (int i = t0; i < BDIM * IDIM / 4; i += stride) {
        float4 v = reinterpret_cast<const float4*>(x)[i];
        __half2 h01, h23; __nv_bfloat162 b01, b23;
        h01.x = __float2half_rn(v.x); b01.x = __float2bfloat16(v.x);
        h01.y = __float2half_rn(v.y); b01.y = __float2bfloat16(v.y);
        h23.x = __float2half_rn(v.z); b23.x = __float2bfloat16(v.z);
        h23.y = __float2half_rn(v.w); b23.y = __float2bfloat16(v.w);
        reinterpret_cast<__half2*>(x16)[i * 2]     = h01;
        reinterpret_cast<__half2*>(x16)[i * 2 + 1] = h23;
        reinterpret_cast<__nv_bfloat162*>(xbf)[i * 2]     = b01;
        reinterpret_cast<__nv_bfloat162*>(xbf)[i * 2 + 1] = b23;
    }
    for (int i = t0; i < HDIM * IDIM / 4; i += stride) {
        float4 v = reinterpret_cast<const float4*>(Wih)[i];
        __half2 h01, h23; __nv_bfloat162 l01, l23;
        splitW(v.x, h01.x, l01.x); splitW(v.y, h01.y, l01.y);
        splitW(v.z, h23.x, l23.x); splitW(v.w, h23.y, l23.y);
        reinterpret_cast<__half2*>(wihhi)[i * 2]     = h01;
        reinterpret_cast<__half2*>(wihhi)[i * 2 + 1] = h23;
        reinterpret_cast<__nv_bfloat162*>(wihlo)[i * 2]     = l01;
        reinterpret_cast<__nv_bfloat162*>(wihlo)[i * 2 + 1] = l23;
    }
    for (int i = t0; i < HDIM * HDIM / 4; i += stride) {
        float4 v = reinterpret_cast<const float4*>(Whh)[i];
        __half2 h01, h23;
        h01.x = __float2half_rn(v.x); h01.y = __float2half_rn(v.y);
        h23.x = __float2half_rn(v.z); h23.y = __float2half_rn(v.w);
        reinterpret_cast<__half2*>(whhhi)[i * 2]     = h01;
        reinterpret_cast<__half2*>(whhhi)[i * 2 + 1] = h23;
    }
    for (int i = t0; i < BDIM * HDIM / 4; i += stride) {
        float4 v = reinterpret_cast<const float4*>(h0)[i];
        reinterpret_cast<float4*>(hfull)[i] = v;
        __half2 h01, h23;
        h01.x = __float2half_rn(v.x); h01.y = __float2half_rn(v.y);
        h23.x = __float2half_rn(v.z); h23.y = __float2half_rn(v.w);
        reinterpret_cast<__half2*>(h16)[i * 2]     = h01;
        reinterpret_cast<__half2*>(h16)[i * 2 + 1] = h23;
    }
}

// ---------------- ih GEMM: 2-term (A16*Whi f16 + Abf*Wlo bf16), warp grid 4x2 ----
__global__ __launch_bounds__(NT, 3)
void ih_kernel(const __half* __restrict__ A16, const __nv_bfloat16* __restrict__ Abf,
               const __half* __restrict__ Whi, const __nv_bfloat16* __restrict__ Wlo,
               int K,
               const float* __restrict__ bih, const float* __restrict__ bhh,
               float* __restrict__ out_full, int ldo) {
    extern __shared__ char sm[];
    float* colv = (float*)(sm + OFF_COLV);
    const uint32_t sb = smem_u32(sm);
    const int tid = threadIdx.x;
    const int lane = tid & 31;
    const int wid = tid >> 5;
    const int wm = wid >> 1, wn = wid & 1;
    const int g = lane >> 2, tig = lane & 3;
    const int n0 = blockIdx.x * BN;
    const int m0 = blockIdx.y * BM;

    for (int j = tid; j < BN; j += NT) colv[j] = bih[n0 + j] + bhh[n0 + j];

    const int lrow = ((lane >> 3) & 1) * 8 + (lane & 7);
    const int lkh  = (lane >> 4);

    const char* gsrc[6];
    uint32_t sdst[6];
    #pragma unroll
    for (int t = 0; t < 6; t++) {
        int idx = tid + t * NT;
        if (idx < 1024) {
            int p = idx >> 9, rem = idx & 511, r = rem >> 2, j = rem & 3;
            sdst[t] = p * A_PLANE + (uint32_t)(r * 64 + ((j ^ ((r >> 1) & 3)) << 4));
            gsrc[t] = (p ? (const char*)Abf : (const char*)A16)
                      + ((size_t)(m0 + r) * K + j * 8) * 2;
        } else {
            int q = idx - 1024;
            int p = q >> 8, rem = q & 255, r = rem >> 2, j = rem & 3;
            sdst[t] = OFF_BPL + p * B_PLANE + (uint32_t)(r * 64 + ((j ^ ((r >> 1) & 3)) << 4));
            gsrc[t] = (p ? (const char*)Wlo : (const char*)Whi)
                      + ((size_t)(n0 + r) * K + j * 8) * 2;
        }
    }
    const int NK = K / BK;
    auto stage = [&](int i, uint32_t base) {
        const int koff = i * BK * 2;
        #pragma unroll
        for (int t = 0; t < 6; t++) cp16(base + sdst[t], gsrc[t] + koff);
    };

    float acc[2][4][4];
    #pragma unroll
    for (int mt = 0; mt < 2; mt++)
        #pragma unroll
        for (int nt = 0; nt < 4; nt++)
            #pragma unroll
            for (int q = 0; q < 4; q++) acc[mt][nt][q] = 0.0f;

    uint32_t aoff[2][2], boff[2][2];
    #pragma unroll
    for (int mt = 0; mt < 2; mt++) {
        const int r = wm * 32 + mt * 16 + lrow;
        const int q = (r >> 1) & 3;
        #pragma unroll
        for (int ks = 0; ks < 2; ks++)
            aoff[mt][ks] = (uint32_t)(r * 64 + (((ks * 2 + lkh) ^ q) << 4));
    }
    #pragma unroll
    for (int nh = 0; nh < 2; nh++) {
        const int r = wn * 32 + nh * 16 + lrow;
        const int q = (r >> 1) & 3;
        #pragma unroll
        for (int ks = 0; ks < 2; ks++)
            boff[nh][ks] = OFF_BPL + (uint32_t)(r * 64 + (((ks * 2 + lkh) ^ q) << 4));
    }

    stage(0, sb); cp_commit();
    stage(1, sb + STAGE_BYTES); cp_commit();
    uint32_t buf = 0;
    for (int i = 0; i < NK; i++) {
        if (i < NK - 1) cp_wait<1>(); else cp_wait<0>();
        __syncthreads();
        if (i + 2 < NK) {
            uint32_t nb = buf + 2; if (nb >= 3) nb -= 3;
            stage(i + 2, sb + nb * STAGE_BYTES);
            cp_commit();
        }
        const uint32_t stg = sb + buf * STAGE_BYTES;
        buf++; if (buf == 3) buf = 0;
        #pragma unroll
        for (int ks = 0; ks < 2; ks++) {
            uint32_t bhx[4], bhy[4], blx[4], bly[4];
            ldsm4(bhx, stg + boff[0][ks]);
            ldsm4(bhy, stg + boff[1][ks]);
            ldsm4(blx, stg + B_PLANE + boff[0][ks]);
            ldsm4(bly, stg + B_PLANE + boff[1][ks]);
            uint32_t bh0[2] = { bhx[0], bhx[2] }, bh1[2] = { bhx[1], bhx[3] };
            uint32_t bh2[2] = { bhy[0], bhy[2] }, bh3[2] = { bhy[1], bhy[3] };
            uint32_t bl0[2] = { blx[0], blx[2] }, bl1[2] = { blx[1], blx[3] };
            uint32_t bl2[2] = { bly[0], bly[2] }, bl3[2] = { bly[1], bly[3] };
            #pragma unroll
            for (int mt = 0; mt < 2; mt++) {
                uint32_t a16[4], abf[4];
                ldsm4(a16, stg + aoff[mt][ks]);
                ldsm4(abf, stg + A_PLANE + aoff[mt][ks]);
                mma_f16 (acc[mt][0], a16, bh0);
                mma_f16 (acc[mt][1], a16, bh1);
                mma_f16 (acc[mt][2], a16, bh2);
                mma_f16 (acc[mt][3], a16, bh3);
                mma_bf16(acc[mt][0], abf, bl0);
                mma_bf16(acc[mt][1], abf, bl1);
                mma_bf16(acc[mt][2], abf, bl2);
                mma_bf16(acc[mt][3], abf, bl3);
            }
        }
    }
    #pragma unroll
    for (int mt = 0; mt < 2; mt++)
        #pragma unroll
        for (int h = 0; h < 2; h++) {
            const int row = m0 + wm * 32 + mt * 16 + g + h * 8;
            const size_t base = (size_t)row * ldo;
            #pragma unroll
            for (int nt = 0; nt < 4; nt++) {
                const int col = n0 + wn * 32 + nt * 8 + tig * 2;
                float2 o = make_float2(acc[mt][nt][h * 2] + colv[col - n0],
                                       acc[mt][nt][h * 2 + 1] + colv[col - n0 + 1]);
                *reinterpret_cast<float2*>(out_full + base + col) = o;
            }
        }
}

// ------- step GEMM v2: 1-term fp16, BN=128, warp grid 2x4 (warp tile 64x32), occ 4
__global__ __launch_bounds__(NT, 4)
void step_kernel(const __half* __restrict__ A16, const __half* __restrict__ W16,
                 const float* __restrict__ ihb, const float* __restrict__ hfull,
                 const float* __restrict__ tau,
                 float* __restrict__ out_full, __half* __restrict__ out_16, int ldo) {
    extern __shared__ char sm[];
    float* colv = (float*)(sm + S_OFF_COLV);
    const uint32_t sb = smem_u32(sm);
    const int K = HDIM;
    const int tid = threadIdx.x;
    const int lane = tid & 31;
    const int wid = tid >> 5;
    const int wm = wid >> 2;      // 0..1 -> 64 rows
    const int wn = wid & 3;       // 0..3 -> 32 cols
    const int g = lane >> 2, tig = lane & 3;
    const int n0 = blockIdx.x * S_BN;
    const int m0 = blockIdx.y * BM;

    for (int j = tid; j < S_BN; j += NT) colv[j] = __expf(-DT / tau[n0 + j]);

    const int lrow = ((lane >> 3) & 1) * 8 + (lane & 7);
    const int lkh  = (lane >> 4);

    // compact staging: sr = tid>>2 (rows sr, sr+64 for A and B), sj = tid&3
    const int sj = tid & 3;
    const int sr = tid >> 2;
    const uint32_t sd = (uint32_t)(sr * 64 + ((sj ^ ((sr >> 1) & 3)) << 4));
    const size_t rowskip = (size_t)64 * K * 2;
    const char* aBase = (const char*)A16 + ((size_t)(m0 + sr) * K + sj * 8) * 2;
    const char* bBase = (const char*)W16 + ((size_t)(n0 + sr) * K + sj * 8) * 2;

    auto stage = [&](int i, uint32_t base) {
        const size_t koff = (size_t)i * (BK * 2);
        cp16(base + sd,                    aBase + koff);
        cp16(base + sd + 4096,             aBase + rowskip + koff);
        cp16(base + S_OFF_B + sd,          bBase + koff);
        cp16(base + S_OFF_B + sd + 4096,   bBase + rowskip + koff);
    };

    float acc[4][4][4];
    #pragma unroll
    for (int mt = 0; mt < 4; mt++)
        #pragma unroll
        for (int nt = 0; nt < 4; nt++)
            #pragma unroll
            for (int q = 0; q < 4; q++) acc[mt][nt][q] = 0.0f;

    uint32_t aO, bO0, bO1;
    {
        const int rA = wm * 64 + lrow;
        aO = (uint32_t)(rA * 64 + ((lkh ^ ((rA >> 1) & 3)) << 4));
        const int rB0 = wn * 32 + lrow;
        bO0 = S_OFF_B + (uint32_t)(rB0 * 64 + ((lkh ^ ((rB0 >> 1) & 3)) << 4));
        const int rB1 = rB0 + 16;
        bO1 = S_OFF_B + (uint32_t)(rB1 * 64 + ((lkh ^ ((rB1 >> 1) & 3)) << 4));
    }

    const int NK = K / BK;
    stage(0, sb); cp_commit();
    stage(1, sb + S_STAGE); cp_commit();
    uint32_t buf = 0;
    for (int i = 0; i < NK; i++) {
        if (i < NK - 1) cp_wait<1>(); else cp_wait<0>();
        __syncthreads();
        if (i + 2 < NK) {
            uint32_t nb = buf + 2; if (nb >= 3) nb -= 3;
            stage(i + 2, sb + nb * S_STAGE);
            cp_commit();
        }
        const uint32_t stg = sb + buf * S_STAGE;
        buf++; if (buf == 3) buf = 0;

        #pragma unroll
        for (int ks = 0; ks < 2; ks++) {
            const uint32_t kx = (uint32_t)(ks << 5);
            uint32_t bhx[4], bhy[4];
            ldsm4(bhx, stg + (bO0 ^ kx));
            ldsm4(bhy, stg + (bO1 ^ kx));
            uint32_t b0[2] = { bhx[0], bhx[2] }, b1[2] = { bhx[1], bhx[3] };
            uint32_t b2[2] = { bhy[0], bhy[2] }, b3[2] = { bhy[1], bhy[3] };
            #pragma unroll
            for (int mt = 0; mt < 4; mt++) {
                uint32_t a16[4];
                ldsm4(a16, stg + ((aO + mt * 1024) ^ kx));
                mma_f16(acc[mt][0], a16, b0);
                mma_f16(acc[mt][1], a16, b1);
                mma_f16(acc[mt][2], a16, b2);
                mma_f16(acc[mt][3], a16, b3);
            }
        }
    }

    #pragma unroll
    for (int mt = 0; mt < 4; mt++)
        #pragma unroll
        for (int h = 0; h < 2; h++) {
            const int row = m0 + wm * 64 + mt * 16 + g + h * 8;
            const size_t base = (size_t)row * ldo;
            #pragma unroll
            for (int nt = 0; nt < 4; nt++) {
                const int col = n0 + wn * 32 + nt * 8 + tig * 2;
                float2 ib = *reinterpret_cast<const float2*>(ihb + base + col);
                float2 hf = *reinterpret_cast<const float2*>(hfull + base + col);
                const float dc0 = colv[col - n0];
                const float dc1 = colv[col - n0 + 1];
                const float hn0 = dc0 * hf.x + (1.0f - dc0) * tanh_acc(acc[mt][nt][h*2]   + ib.x);
                const float hn1 = dc1 * hf.y + (1.0f - dc1) * tanh_acc(acc[mt][nt][h*2+1] + ib.y);
                *reinterpret_cast<float2*>(out_full + base + col) = make_float2(hn0, hn1);
                __half2 hp;
                hp.x = __float2half_rn(hn0);
                hp.y = __float2half_rn(hn1);
                *reinterpret_cast<__half2*>(out_16 + base + col) = hp;
            }
        }
}

extern "C" void kernel_launch(void* const* d_in, const int* in_sizes, int n_in,
                              void* d_out, int out_size) {
    (void)in_sizes; (void)n_in; (void)out_size;
    const float* x   = (const float*)d_in[0];
    const float* h0  = (const float*)d_in[1];
    const float* Wih = (const float*)d_in[2];
    const float* bih = (const float*)d_in[3];
    const float* Whh = (const float*)d_in[4];
    const float* bhh = (const float*)d_in[5];
    const float* tau = (const float*)d_in[6];
    float* out = (float*)d_out;

    float *p_ihb, *p_hfull;
    __half *p_h16A, *p_h16B, *p_x16, *p_wihhi, *p_whhhi;
    __nv_bfloat16 *p_xbf, *p_wihlo;
    cudaGetSymbolAddress((void**)&p_ihb, g_ihb);
    cudaGetSymbolAddress((void**)&p_hfull, g_hfull);
    cudaGetSymbolAddress((void**)&p_h16A, g_h16A);
    cudaGetSymbolAddress((void**)&p_h16B, g_h16B);
    cudaGetSymbolAddress((void**)&p_x16, g_x16);
    cudaGetSymbolAddress((void**)&p_xbf, g_xbf);
    cudaGetSymbolAddress((void**)&p_wihhi, g_wihhi);
    cudaGetSymbolAddress((void**)&p_wihlo, g_wihlo);
    cudaGetSymbolAddress((void**)&p_whhhi, g_whhhi);

    cudaFuncSetAttribute(ih_kernel,   cudaFuncAttributeMaxDynamicSharedMemorySize, SMEM_TOTAL);
    cudaFuncSetAttribute(step_kernel, cudaFuncAttributeMaxDynamicSharedMemorySize, S_SMEM_TOTAL);

    prep_all_kernel<<<512, 256>>>(x, Wih, Whh, h0,
                                  p_x16, p_xbf, p_wihhi, p_wihlo, p_whhhi,
                                  p_hfull, p_h16A);

    dim3 grid_ih(HDIM / BN, BDIM / BM);      // 32 x 32
    ih_kernel<<<grid_ih, NT, SMEM_TOTAL>>>(p_x16, p_xbf, p_wihhi, p_wihlo, IDIM,
                                           bih, bhh, p_ihb, HDIM);
    dim3 grid_st(HDIM / S_BN, BDIM / BM);    // 16 x 32 = 512 CTAs (single wave @ occ 4)
    __half *h16_in = p_h16A, *h16_out = p_h16B;
    for (int s = 0; s < NSTEPS; s++) {
        float* full_dst = (s == NSTEPS - 1) ? out : p_hfull;
        step_kernel<<<grid_st, NT, S_SMEM_TOTAL>>>(h16_in, p_whhhi,
                                                   p_ihb, p_hfull, tau,
                                                   full_dst, h16_out, HDIM);
        __half* t16 = h16_in; h16_in = h16_out; h16_out = t16;
    }
}

// round 17
// speedup vs baseline: 3.4256x; 3.4256x over previous
#include <cuda_runtime.h>
#include <cuda_bf16.h>
#include <cuda_fp16.h>
#include <cstdint>

static constexpr int BDIM = 4096;
static constexpr int IDIM = 1024;
static constexpr int HDIM = 2048;
static constexpr int NSTEPS = 10;
static constexpr float DT = 0.1f;

static constexpr int BM = 128, BN = 64, BK = 32;
static constexpr int NT = 256;

// ---- ih kernel (2-term): stage [A16 8K | Abf 8K | Bhi 4K | Blo 4K] = 24 KB, 3 stages
static constexpr int A_PLANE = BM * BK * 2;            // 8 KB
static constexpr int B_PLANE = BN * BK * 2;            // 4 KB
static constexpr int STAGE_BYTES = 2 * A_PLANE + 2 * B_PLANE;   // 24 KB
static constexpr int OFF_BPL = 2 * A_PLANE;            // 16 KB
static constexpr int OFF_COLV = 3 * STAGE_BYTES;       // 72 KB
static constexpr int SMEM_TOTAL = OFF_COLV + BN * 4 + 16;

// ---- step kernel (1-term fp16): stage [A16 8K | B16 4K] = 12 KB, 3 stages
static constexpr int S_STAGE = A_PLANE + B_PLANE;      // 12 KB
static constexpr int S_OFF_B = A_PLANE;                // 8 KB
static constexpr int S_OFF_COLV = 3 * S_STAGE;         // 36 KB
static constexpr int S_SMEM_TOTAL = S_OFF_COLV + BN * 4 + 16;   // ~36.3 KB -> occ 4

__device__ float g_ihb  [BDIM * HDIM];
__device__ float g_hfull[BDIM * HDIM];
__device__ __half        g_h16A[BDIM * HDIM];
__device__ __half        g_h16B[BDIM * HDIM];
__device__ __half        g_x16 [BDIM * IDIM];
__device__ __nv_bfloat16 g_xbf [BDIM * IDIM];
__device__ __half        g_wihhi[HDIM * IDIM];
__device__ __nv_bfloat16 g_wihlo[HDIM * IDIM];
__device__ __half        g_whhhi[HDIM * HDIM];

__device__ __forceinline__ uint32_t smem_u32(const void* p) {
    uint32_t a;
    asm("{ .reg .u64 t; cvta.to.shared.u64 t, %1; cvt.u32.u64 %0, t; }" : "=r"(a) : "l"(p));
    return a;
}
__device__ __forceinline__ void cp16(uint32_t dst, const void* src) {
    asm volatile("cp.async.cg.shared.global [%0], [%1], 16;" :: "r"(dst), "l"(src) : "memory");
}
__device__ __forceinline__ void cp_commit() { asm volatile("cp.async.commit_group;" ::: "memory"); }
template <int N> __device__ __forceinline__ void cp_wait() {
    asm volatile("cp.async.wait_group %0;" :: "n"(N) : "memory");
}
__device__ __forceinline__ float tanh_acc(float x) {
    float ax = fabsf(x);
    float e = __expf(-2.0f * ax);
    float t = (1.0f - e) / (1.0f + e);
    return copysignf(t, x);
}
__device__ __forceinline__ void mma_f16(float* c, const uint32_t* a, const uint32_t* b) {
    asm volatile(
        "mma.sync.aligned.m16n8k16.row.col.f32.f16.f16.f32 "
        "{%0,%1,%2,%3},{%4,%5,%6,%7},{%8,%9},{%0,%1,%2,%3};"
        : "+f"(c[0]), "+f"(c[1]), "+f"(c[2]), "+f"(c[3])
        : "r"(a[0]), "r"(a[1]), "r"(a[2]), "r"(a[3]), "r"(b[0]), "r"(b[1]));
}
__device__ __forceinline__ void mma_bf16(float* c, const uint32_t* a, const uint32_t* b) {
    asm volatile(
        "mma.sync.aligned.m16n8k16.row.col.f32.bf16.bf16.f32 "
        "{%0,%1,%2,%3},{%4,%5,%6,%7},{%8,%9},{%0,%1,%2,%3};"
        : "+f"(c[0]), "+f"(c[1]), "+f"(c[2]), "+f"(c[3])
        : "r"(a[0]), "r"(a[1]), "r"(a[2]), "r"(a[3]), "r"(b[0]), "r"(b[1]));
}
__device__ __forceinline__ void ldsm4(uint32_t* r, uint32_t addr) {
    asm volatile("ldmatrix.sync.aligned.m8n8.x4.shared.b16 {%0,%1,%2,%3}, [%4];"
                 : "=r"(r[0]), "=r"(r[1]), "=r"(r[2]), "=r"(r[3]) : "r"(addr));
}
__device__ __forceinline__ void splitW(float v, __half& hi, __nv_bfloat16& lo) {
    hi = __float2half_rn(v);
    lo = __float2bfloat16(v - __half2float(hi));
}

__global__ void prep_all_kernel(const float* __restrict__ x,
                                const float* __restrict__ Wih,
                                const float* __restrict__ Whh,
                                const float* __restrict__ h0,
                                __half* __restrict__ x16, __nv_bfloat16* __restrict__ xbf,
                                __half* __restrict__ wihhi, __nv_bfloat16* __restrict__ wihlo,
                                __half* __restrict__ whhhi,
                                float* __restrict__ hfull, __half* __restrict__ h16) {
    const int stride = gridDim.x * blockDim.x;
    const int t0 = blockIdx.x * blockDim.x + threadIdx.x;
    for (int i = t0; i < BDIM * IDIM / 4; i += stride) {
        float4 v = reinterpret_cast<const float4*>(x)[i];
        __half2 h01, h23; __nv_bfloat162 b01, b23;
        h01.x = __float2half_rn(v.x); b01.x = __float2bfloat16(v.x);
        h01.y = __float2half_rn(v.y); b01.y = __float2bfloat16(v.y);
        h23.x = __float2half_rn(v.z); b23.x = __float2bfloat16(v.z);
        h23.y = __float2half_rn(v.w); b23.y = __float2bfloat16(v.w);
        reinterpret_cast<__half2*>(x16)[i * 2]     = h01;
        reinterpret_cast<__half2*>(x16)[i * 2 + 1] = h23;
        reinterpret_cast<__nv_bfloat162*>(xbf)[i * 2]     = b01;
        reinterpret_cast<__nv_bfloat162*>(xbf)[i * 2 + 1] = b23;
    }
    for (int i = t0; i < HDIM * IDIM / 4; i += stride) {
        float4 v = reinterpret_cast<const float4*>(Wih)[i];
        __half2 h01, h23; __nv_bfloat162 l01, l23;
        splitW(v.x, h01.x, l01.x); splitW(v.y, h01.y, l01.y);
        splitW(v.z, h23.x, l23.x); splitW(v.w, h23.y, l23.y);
        reinterpret_cast<__half2*>(wihhi)[i * 2]     = h01;
        reinterpret_cast<__half2*>(wihhi)[i * 2 + 1] = h23;
        reinterpret_cast<__nv_bfloat162*>(wihlo)[i * 2]     = l01;
        reinterpret_cast<__nv_bfloat162*>(wihlo)[i * 2 + 1] = l23;
    }
    for (int i = t0; i < HDIM * HDIM / 4; i += stride) {
        float4 v = reinterpret_cast<const float4*>(Whh)[i];
        __half2 h01, h23;
        h01.x = __float2half_rn(v.x); h01.y = __float2half_rn(v.y);
        h23.x = __float2half_rn(v.z); h23.y = __float2half_rn(v.w);
        reinterpret_cast<__half2*>(whhhi)[i * 2]     = h01;
        reinterpret_cast<__half2*>(whhhi)[i * 2 + 1] = h23;
    }
    for (int i = t0; i < BDIM * HDIM / 4; i += stride) {
        float4 v = reinterpret_cast<const float4*>(h0)[i];
        reinterpret_cast<float4*>(hfull)[i] = v;
        __half2 h01, h23;
        h01.x = __float2half_rn(v.x); h01.y = __float2half_rn(v.y);
        h23.x = __float2half_rn(v.z); h23.y = __float2half_rn(v.w);
        reinterpret_cast<__half2*>(h16)[i * 2]     = h01;
        reinterpret_cast<__half2*>(h16)[i * 2 + 1] = h23;
    }
}

// ---------------- ih GEMM: 2-term (A16*Whi f16 + Abf*Wlo bf16), warp grid 4x2 ----
__global__ __launch_bounds__(NT, 3)
void ih_kernel(const __half* __restrict__ A16, const __nv_bfloat16* __restrict__ Abf,
               const __half* __restrict__ Whi, const __nv_bfloat16* __restrict__ Wlo,
               int K,
               const float* __restrict__ bih, const float* __restrict__ bhh,
               float* __restrict__ out_full, int ldo) {
    extern __shared__ char sm[];
    float* colv = (float*)(sm + OFF_COLV);
    const uint32_t sb = smem_u32(sm);
    const int tid = threadIdx.x;
    const int lane = tid & 31;
    const int wid = tid >> 5;
    const int wm = wid >> 1, wn = wid & 1;
    const int g = lane >> 2, tig = lane & 3;
    const int n0 = blockIdx.x * BN;
    const int m0 = blockIdx.y * BM;

    for (int j = tid; j < BN; j += NT) colv[j] = bih[n0 + j] + bhh[n0 + j];

    const int lrow = ((lane >> 3) & 1) * 8 + (lane & 7);
    const int lkh  = (lane >> 4);

    const char* gsrc[6];
    uint32_t sdst[6];
    #pragma unroll
    for (int t = 0; t < 6; t++) {
        int idx = tid + t * NT;
        if (idx < 1024) {
            int p = idx >> 9, rem = idx & 511, r = rem >> 2, j = rem & 3;
            sdst[t] = p * A_PLANE + (uint32_t)(r * 64 + ((j ^ ((r >> 1) & 3)) << 4));
            gsrc[t] = (p ? (const char*)Abf : (const char*)A16)
                      + ((size_t)(m0 + r) * K + j * 8) * 2;
        } else {
            int q = idx - 1024;
            int p = q >> 8, rem = q & 255, r = rem >> 2, j = rem & 3;
            sdst[t] = OFF_BPL + p * B_PLANE + (uint32_t)(r * 64 + ((j ^ ((r >> 1) & 3)) << 4));
            gsrc[t] = (p ? (const char*)Wlo : (const char*)Whi)
                      + ((size_t)(n0 + r) * K + j * 8) * 2;
        }
    }
    const int NK = K / BK;
    auto stage = [&](int i, uint32_t base) {
        const int koff = i * BK * 2;
        #pragma unroll
        for (int t = 0; t < 6; t++) cp16(base + sdst[t], gsrc[t] + koff);
    };

    float acc[2][4][4];
    #pragma unroll
    for (int mt = 0; mt < 2; mt++)
        #pragma unroll
        for (int nt = 0; nt < 4; nt++)
            #pragma unroll
            for (int q = 0; q < 4; q++) acc[mt][nt][q] = 0.0f;

    uint32_t aoff[2][2], boff[2][2];
    #pragma unroll
    for (int mt = 0; mt < 2; mt++) {
        const int r = wm * 32 + mt * 16 + lrow;
        const int q = (r >> 1) & 3;
        #pragma unroll
        for (int ks = 0; ks < 2; ks++)
            aoff[mt][ks] = (uint32_t)(r * 64 + (((ks * 2 + lkh) ^ q) << 4));
    }
    #pragma unroll
    for (int nh = 0; nh < 2; nh++) {
        const int r = wn * 32 + nh * 16 + lrow;
        const int q = (r >> 1) & 3;
        #pragma unroll
        for (int ks = 0; ks < 2; ks++)
            boff[nh][ks] = OFF_BPL + (uint32_t)(r * 64 + (((ks * 2 + lkh) ^ q) << 4));
    }

    stage(0, sb); cp_commit();
    stage(1, sb + STAGE_BYTES); cp_commit();
    uint32_t buf = 0;
    for (int i = 0; i < NK; i++) {
        if (i < NK - 1) cp_wait<1>(); else cp_wait<0>();
        __syncthreads();
        if (i + 2 < NK) {
            uint32_t nb = buf + 2; if (nb >= 3) nb -= 3;
            stage(i + 2, sb + nb * STAGE_BYTES);
            cp_commit();
        }
        const uint32_t stg = sb + buf * STAGE_BYTES;
        buf++; if (buf == 3) buf = 0;
        #pragma unroll
        for (int ks = 0; ks < 2; ks++) {
            uint32_t bhx[4], bhy[4], blx[4], bly[4];
            ldsm4(bhx, stg + boff[0][ks]);
            ldsm4(bhy, stg + boff[1][ks]);
            ldsm4(blx, stg + B_PLANE + boff[0][ks]);
            ldsm4(bly, stg + B_PLANE + boff[1][ks]);
            uint32_t bh0[2] = { bhx[0], bhx[2] }, bh1[2] = { bhx[1], bhx[3] };
            uint32_t bh2[2] = { bhy[0], bhy[2] }, bh3[2] = { bhy[1], bhy[3] };
            uint32_t bl0[2] = { blx[0], blx[2] }, bl1[2] = { blx[1], blx[3] };
            uint32_t bl2[2] = { bly[0], bly[2] }, bl3[2] = { bly[1], bly[3] };
            #pragma unroll
            for (int mt = 0; mt < 2; mt++) {
                uint32_t a16[4], abf[4];
                ldsm4(a16, stg + aoff[mt][ks]);
                ldsm4(abf, stg + A_PLANE + aoff[mt][ks]);
                mma_f16 (acc[mt][0], a16, bh0);
                mma_f16 (acc[mt][1], a16, bh1);
                mma_f16 (acc[mt][2], a16, bh2);
                mma_f16 (acc[mt][3], a16, bh3);
                mma_bf16(acc[mt][0], abf, bl0);
                mma_bf16(acc[mt][1], abf, bl1);
                mma_bf16(acc[mt][2], abf, bl2);
                mma_bf16(acc[mt][3], abf, bl3);
            }
        }
    }
    #pragma unroll
    for (int mt = 0; mt < 2; mt++)
        #pragma unroll
        for (int h = 0; h < 2; h++) {
            const int row = m0 + wm * 32 + mt * 16 + g + h * 8;
            const size_t base = (size_t)row * ldo;
            #pragma unroll
            for (int nt = 0; nt < 4; nt++) {
                const int col = n0 + wn * 32 + nt * 8 + tig * 2;
                float2 o = make_float2(acc[mt][nt][h * 2] + colv[col - n0],
                                       acc[mt][nt][h * 2 + 1] + colv[col - n0 + 1]);
                *reinterpret_cast<float2*>(out_full + base + col) = o;
            }
        }
}

// ---------------- step GEMM: 1-term fp16 (A16*W16), warp grid 4x2, occ 4 ----------
__global__ __launch_bounds__(NT, 4)
void step_kernel(const __half* __restrict__ A16, const __half* __restrict__ W16,
                 const float* __restrict__ ihb, const float* __restrict__ hfull,
                 const float* __restrict__ tau,
                 float* __restrict__ out_full, __half* __restrict__ out_16, int ldo) {
    extern __shared__ char sm[];
    float* colv = (float*)(sm + S_OFF_COLV);
    const uint32_t sb = smem_u32(sm);
    const int K = HDIM;
    const int tid = threadIdx.x;
    const int lane = tid & 31;
    const int wid = tid >> 5;
    const int wm = wid >> 1, wn = wid & 1;
    const int g = lane >> 2, tig = lane & 3;
    const int n0 = blockIdx.x * BN;
    const int m0 = blockIdx.y * BM;

    for (int j = tid; j < BN; j += NT) colv[j] = __expf(-DT / tau[n0 + j]);

    const int lrow = ((lane >> 3) & 1) * 8 + (lane & 7);
    const int lkh  = (lane >> 4);

    // staging: 768 chunks/stage (A:512, B:256), 3 per thread
    const char* gsrc[3];
    uint32_t sdst[3];
    #pragma unroll
    for (int t = 0; t < 3; t++) {
        int idx = tid + t * NT;
        if (idx < 512) {
            int r = idx >> 2, j = idx & 3;
            sdst[t] = (uint32_t)(r * 64 + ((j ^ ((r >> 1) & 3)) << 4));
            gsrc[t] = (const char*)A16 + ((size_t)(m0 + r) * K + j * 8) * 2;
        } else {
            int q = idx - 512;
            int r = q >> 2, j = q & 3;
            sdst[t] = S_OFF_B + (uint32_t)(r * 64 + ((j ^ ((r >> 1) & 3)) << 4));
            gsrc[t] = (const char*)W16 + ((size_t)(n0 + r) * K + j * 8) * 2;
        }
    }
    const int NK = K / BK;
    auto stage = [&](int i, uint32_t base) {
        const int koff = i * BK * 2;
        #pragma unroll
        for (int t = 0; t < 3; t++) cp16(base + sdst[t], gsrc[t] + koff);
    };

    float acc[2][4][4];
    #pragma unroll
    for (int mt = 0; mt < 2; mt++)
        #pragma unroll
        for (int nt = 0; nt < 4; nt++)
            #pragma unroll
            for (int q = 0; q < 4; q++) acc[mt][nt][q] = 0.0f;

    uint32_t aoff[2][2], boff[2][2];
    #pragma unroll
    for (int mt = 0; mt < 2; mt++) {
        const int r = wm * 32 + mt * 16 + lrow;
        const int q = (r >> 1) & 3;
        #pragma unroll
        for (int ks = 0; ks < 2; ks++)
            aoff[mt][ks] = (uint32_t)(r * 64 + (((ks * 2 + lkh) ^ q) << 4));
    }
    #pragma unroll
    for (int nh = 0; nh < 2; nh++) {
        const int r = wn * 32 + nh * 16 + lrow;
        const int q = (r >> 1) & 3;
        #pragma unroll
        for (int ks = 0; ks < 2; ks++)
            boff[nh][ks] = S_OFF_B + (uint32_t)(r * 64 + (((ks * 2 + lkh) ^ q) << 4));
    }

    stage(0, sb); cp_commit();
    stage(1, sb + S_STAGE); cp_commit();
    uint32_t buf = 0;
    for (int i = 0; i < NK; i++) {
        if (i < NK - 1) cp_wait<1>(); else cp_wait<0>();
        __syncthreads();
        if (i + 2 < NK) {
            uint32_t nb = buf + 2; if (nb >= 3) nb -= 3;
            stage(i + 2, sb + nb * S_STAGE);
            cp_commit();
        }
        const uint32_t stg = sb + buf * S_STAGE;
        buf++; if (buf == 3) buf = 0;
        #pragma unroll
        for (int ks = 0; ks < 2; ks++) {
            uint32_t bhx[4], bhy[4];
            ldsm4(bhx, stg + boff[0][ks]);
            ldsm4(bhy, stg + boff[1][ks]);
            uint32_t b0[2] = { bhx[0], bhx[2] }, b1[2] = { bhx[1], bhx[3] };
            uint32_t b2[2] = { bhy[0], bhy[2] }, b3[2] = { bhy[1], bhy[3] };
            #pragma unroll
            for (int mt = 0; mt < 2; mt++) {
                uint32_t a16[4];
                ldsm4(a16, stg + aoff[mt][ks]);
                mma_f16(acc[mt][0], a16, b0);
                mma_f16(acc[mt][1], a16, b1);
                mma_f16(acc[mt][2], a16, b2);
                mma_f16(acc[mt][3], a16, b3);
            }
        }
    }

    const bool write16 = (out_16 != nullptr);
    #pragma unroll
    for (int mt = 0; mt < 2; mt++)
        #pragma unroll
        for (int h = 0; h < 2; h++) {
            const int row = m0 + wm * 32 + mt * 16 + g + h * 8;
            const size_t base = (size_t)row * ldo;
            #pragma unroll
            for (int nt = 0; nt < 4; nt++) {
                const int col = n0 + wn * 32 + nt * 8 + tig * 2;
                float2 ib = *reinterpret_cast<const float2*>(ihb + base + col);
                float2 hf = *reinterpret_cast<const float2*>(hfull + base + col);
                const float dc0 = colv[col - n0];
                const float dc1 = colv[col - n0 + 1];
                const float hn0 = dc0 * hf.x + (1.0f - dc0) * tanh_acc(acc[mt][nt][h*2]   + ib.x);
                const float hn1 = dc1 * hf.y + (1.0f - dc1) * tanh_acc(acc[mt][nt][h*2+1] + ib.y);
                *reinterpret_cast<float2*>(out_full + base + col) = make_float2(hn0, hn1);
                if (write16) {
                    __half2 hp;
                    hp.x = __float2half_rn(hn0);
                    hp.y = __float2half_rn(hn1);
                    *reinterpret_cast<__half2*>(out_16 + base + col) = hp;
                }
            }
        }
}

extern "C" void kernel_launch(void* const* d_in, const int* in_sizes, int n_in,
                              void* d_out, int out_size) {
    (void)in_sizes; (void)n_in; (void)out_size;
    const float* x   = (const float*)d_in[0];
    const float* h0  = (const float*)d_in[1];
    const float* Wih = (const float*)d_in[2];
    const float* bih = (const float*)d_in[3];
    const float* Whh = (const float*)d_in[4];
    const float* bhh = (const float*)d_in[5];
    const float* tau = (const float*)d_in[6];
    float* out = (float*)d_out;

    float *p_ihb, *p_hfull;
    __half *p_h16A, *p_h16B, *p_x16, *p_wihhi, *p_whhhi;
    __nv_bfloat16 *p_xbf, *p_wihlo;
    cudaGetSymbolAddress((void**)&p_ihb, g_ihb);
    cudaGetSymbolAddress((void**)&p_hfull, g_hfull);
    cudaGetSymbolAddress((void**)&p_h16A, g_h16A);
    cudaGetSymbolAddress((void**)&p_h16B, g_h16B);
    cudaGetSymbolAddress((void**)&p_x16, g_x16);
    cudaGetSymbolAddress((void**)&p_xbf, g_xbf);
    cudaGetSymbolAddress((void**)&p_wihhi, g_wihhi);
    cudaGetSymbolAddress((void**)&p_wihlo, g_wihlo);
    cudaGetSymbolAddress((void**)&p_whhhi, g_whhhi);

    cudaFuncSetAttribute(ih_kernel,   cudaFuncAttributeMaxDynamicSharedMemorySize, SMEM_TOTAL);
    cudaFuncSetAttribute(step_kernel, cudaFuncAttributeMaxDynamicSharedMemorySize, S_SMEM_TOTAL);

    prep_all_kernel<<<512, 256>>>(x, Wih, Whh, h0,
                                  p_x16, p_xbf, p_wihhi, p_wihlo, p_whhhi,
                                  p_hfull, p_h16A);

    dim3 grid(HDIM / BN, BDIM / BM);   // 32 x 32 = 1024 CTAs
    ih_kernel<<<grid, NT, SMEM_TOTAL>>>(p_x16, p_xbf, p_wihhi, p_wihlo, IDIM,
                                        bih, bhh, p_ihb, HDIM);
    __half *h16_in = p_h16A, *h16_out = p_h16B;
    for (int s = 0; s < NSTEPS; s++) {
        const bool last = (s == NSTEPS - 1);
        float* full_dst = last ? out : p_hfull;
        step_kernel<<<grid, NT, S_SMEM_TOTAL>>>(h16_in, p_whhhi,
                                                p_ihb, p_hfull, tau,
                                                full_dst, last ? nullptr : h16_out, HDIM);
        __half* t16 = h16_in; h16_in = h16_out; h16_out = t16;
    }
}